// round 2
// baseline (speedup 1.0000x reference)
#include <cuda_runtime.h>
#include <float.h>

#define BB 32
#define NN 4096
#define DD 768
#define CC 10
#define KSEL 16

// scratch scores [B, N] — __device__ global (no allocations allowed)
__device__ float g_scores[BB * NN];

// Kernel 1: s[b,n] = H[b,n,:] . w_score + b_score
// One warp per row; each lane handles 6 float4 (24 floats) of the 768-dim row.
// All 6 global loads are issued before any FMA so they overlap (MLP=6).
__global__ __launch_bounds__(256) void score_kernel(
    const float* __restrict__ H,
    const float* __restrict__ w,
    const float* __restrict__ b_score)
{
    __shared__ float4 wsh[DD / 4];  // 768 floats = 192 float4
    int tid = threadIdx.x;
    for (int i = tid; i < DD / 4; i += blockDim.x)
        wsh[i] = reinterpret_cast<const float4*>(w)[i];
    __syncthreads();

    int warp = tid >> 5;
    int lane = tid & 31;
    int row  = blockIdx.x * 8 + warp;  // 131072 rows total

    const float4* h = reinterpret_cast<const float4*>(H + (size_t)row * DD);

    float4 a[6];
#pragma unroll
    for (int i = 0; i < 6; i++)
        a[i] = h[lane + i * 32];

    float acc = 0.0f;
#pragma unroll
    for (int i = 0; i < 6; i++) {
        float4 wv = wsh[lane + i * 32];
        acc += a[i].x * wv.x + a[i].y * wv.y + a[i].z * wv.z + a[i].w * wv.w;
    }
#pragma unroll
    for (int off = 16; off; off >>= 1)
        acc += __shfl_down_sync(0xffffffffu, acc, off);

    if (lane == 0)
        g_scores[row] = acc + b_score[0];
}

// Kernel 2: per-batch top-16 selection, A scatter, mean-pool, classifier GEMV.
// One block (256 threads) per batch. Fully deterministic (no atomics).
__global__ __launch_bounds__(256) void topk_kernel(
    const float* __restrict__ H,
    const float* __restrict__ W_cls,
    const float* __restrict__ b_cls,
    float* __restrict__ out)
{
    int b   = blockIdx.x;
    int tid = threadIdx.x;

    __shared__ float s[NN];          // 16 KB
    __shared__ float M[DD];          // 3 KB
    __shared__ int   topk[KSEL];
    __shared__ float rv[256];
    __shared__ int   ri[256];
    __shared__ float wred[8 * CC];   // per-warp partial logits

    float*       A  = out + BB * CC + (size_t)b * NN;
    const float* sg = g_scores + b * NN;

    // load scores to shared; zero this batch's A slice
    for (int i = tid; i < NN; i += 256) {
        s[i] = sg[i];
        A[i] = 0.0f;
    }
    __syncthreads();

    // 16 iterations of argmax with lowest-index tie-break (matches lax.top_k)
    for (int k = 0; k < KSEL; k++) {
        float bv = -FLT_MAX;
        int   bi = NN;  // sentinel larger than any valid index
        for (int i = tid; i < NN; i += 256) {
            float v = s[i];
            if (v > bv || (v == bv && i < bi)) { bv = v; bi = i; }
        }
        rv[tid] = bv;
        ri[tid] = bi;
        __syncthreads();
        for (int off = 128; off; off >>= 1) {
            if (tid < off) {
                float ov = rv[tid + off];
                int   oi = ri[tid + off];
                if (ov > rv[tid] || (ov == rv[tid] && oi < ri[tid])) {
                    rv[tid] = ov;
                    ri[tid] = oi;
                }
            }
            __syncthreads();
        }
        if (tid == 0) {
            topk[k] = ri[0];
            s[ri[0]] = -FLT_MAX;  // remove from further selection
        }
        __syncthreads();
    }

    // scatter A: 1/16 at each selected index
    if (tid < KSEL)
        A[topk[tid]] = 1.0f / (float)KSEL;

    // M = mean over the 16 selected rows; each thread owns 3 dims
    for (int d = tid; d < DD; d += 256) {
        float acc = 0.0f;
#pragma unroll
        for (int k = 0; k < KSEL; k++)
            acc += H[((size_t)b * NN + topk[k]) * DD + d];
        M[d] = acc * (1.0f / (float)KSEL);
    }
    __syncthreads();

    // logits = M @ W_cls + b_cls, deterministic reduction:
    // thread partials -> warp shuffle tree -> 8 warp partials -> serial sum.
    float part[CC];
#pragma unroll
    for (int c = 0; c < CC; c++) part[c] = 0.0f;
    for (int d = tid; d < DD; d += 256) {
        float m = M[d];
#pragma unroll
        for (int c = 0; c < CC; c++)
            part[c] += m * W_cls[d * CC + c];
    }
    int lane = tid & 31, warp = tid >> 5;
#pragma unroll
    for (int c = 0; c < CC; c++) {
        float v = part[c];
#pragma unroll
        for (int off = 16; off; off >>= 1)
            v += __shfl_down_sync(0xffffffffu, v, off);
        if (lane == 0) wred[warp * CC + c] = v;
    }
    __syncthreads();

    if (tid < CC) {
        float acc = b_cls[tid];
#pragma unroll
        for (int wv = 0; wv < 8; wv++)
            acc += wred[wv * CC + tid];
        out[b * CC + tid] = acc;
    }
}

extern "C" void kernel_launch(void* const* d_in, const int* in_sizes, int n_in,
                              void* d_out, int out_size)
{
    const float* H   = (const float*)d_in[0];
    const float* w   = (const float*)d_in[1];
    const float* bs  = (const float*)d_in[2];
    const float* Wc  = (const float*)d_in[3];
    const float* bc  = (const float*)d_in[4];
    float*       out = (float*)d_out;

    // 131072 rows, 8 warps (rows) per block
    score_kernel<<<(BB * NN) / 8, 256>>>(H, w, bs);
    topk_kernel<<<BB, 256>>>(H, Wc, bc, out);
}

// round 14
// speedup vs baseline: 1.3959x; 1.3959x over previous
#include <cuda_runtime.h>
#include <float.h>

#define BB 32
#define NN 4096
#define DD 768
#define CC 10
#define KSEL 16

// scratch scores [B, N] — __device__ global (no allocations allowed)
__device__ float g_scores[BB * NN];

// Kernel 1: s[b,n] = H[b,n,:] . w_score + b_score
// One warp per row; each lane handles 6 float4 (24 floats) of the 768-dim row.
__global__ __launch_bounds__(256) void score_kernel(
    const float* __restrict__ H,
    const float* __restrict__ w,
    const float* __restrict__ b_score)
{
    __shared__ float4 wsh[DD / 4];  // 192 float4
    int tid = threadIdx.x;
    for (int i = tid; i < DD / 4; i += blockDim.x)
        wsh[i] = reinterpret_cast<const float4*>(w)[i];
    __syncthreads();

    int warp = tid >> 5;
    int lane = tid & 31;
    int row  = blockIdx.x * 8 + warp;  // 131072 rows total

    const float4* h = reinterpret_cast<const float4*>(H + (size_t)row * DD);

    float4 a[6];
#pragma unroll
    for (int i = 0; i < 6; i++)
        a[i] = h[lane + i * 32];

    float acc = 0.0f;
#pragma unroll
    for (int i = 0; i < 6; i++) {
        float4 wv = wsh[lane + i * 32];
        acc += a[i].x * wv.x + a[i].y * wv.y + a[i].z * wv.z + a[i].w * wv.w;
    }
#pragma unroll
    for (int off = 16; off; off >>= 1)
        acc += __shfl_down_sync(0xffffffffu, acc, off);

    if (lane == 0)
        g_scores[row] = acc + b_score[0];
}

// combine two (value, index) candidates; lowest index wins ties
__device__ __forceinline__ void cand_take(float& bv, int& bi, float ov, int oi) {
    if (ov > bv || (ov == bv && oi < bi)) { bv = ov; bi = oi; }
}

// Kernel 2: per-batch top-16 via register-cached candidates, A scatter,
// mean-pool, classifier GEMV. One block (256 threads) per batch.
__global__ __launch_bounds__(256) void topk_kernel(
    const float* __restrict__ H,
    const float* __restrict__ W_cls,
    const float* __restrict__ b_cls,
    float* __restrict__ out)
{
    int b    = blockIdx.x;
    int tid  = threadIdx.x;
    int lane = tid & 31;
    int warp = tid >> 5;

    __shared__ float wv_s[8];
    __shared__ int   wi_s[8];
    __shared__ int   win;
    __shared__ int   topk_sh[KSEL];
    __shared__ float M[DD];
    __shared__ float wred[8 * CC];

    float*       A  = out + BB * CC + (size_t)b * NN;
    const float* sg = g_scores + b * NN;

    // each thread owns global indices i = j*256 + tid, j = 0..15, in registers
    float sl[16];
#pragma unroll
    for (int j = 0; j < 16; j++)
        sl[j] = sg[j * 256 + tid];

    // zero A slice (coalesced, overlaps with selection latency)
    float4 zero4 = make_float4(0.f, 0.f, 0.f, 0.f);
#pragma unroll
    for (int j = 0; j < 4; j++)
        reinterpret_cast<float4*>(A)[j * 256 + tid] = zero4;

    // local candidate (strict > keeps lowest j => lowest global index per thread)
    float cv = sl[0]; int cj = 0;
#pragma unroll
    for (int j = 1; j < 16; j++)
        if (sl[j] > cv) { cv = sl[j]; cj = j; }
    int ci = cj * 256 + tid;

    // 16 selection passes over 256 cached candidates
    for (int k = 0; k < KSEL; k++) {
        float v = cv; int i = ci;
#pragma unroll
        for (int off = 16; off; off >>= 1) {
            float ov = __shfl_down_sync(0xffffffffu, v, off);
            int   oi = __shfl_down_sync(0xffffffffu, i, off);
            cand_take(v, i, ov, oi);
        }
        if (lane == 0) { wv_s[warp] = v; wi_s[warp] = i; }
        __syncthreads();                      // (1) warp winners ready
        if (tid == 0) {
            float bv = wv_s[0]; int bi = wi_s[0];
#pragma unroll
            for (int wq = 1; wq < 8; wq++)
                cand_take(bv, bi, wv_s[wq], wi_s[wq]);
            win = bi;
            topk_sh[k] = bi;
        }
        __syncthreads();                      // (2) winner broadcast; wv_s safe to reuse
        int w = win;
        if ((w & 255) == tid) {               // owner invalidates + recomputes
            sl[w >> 8] = -FLT_MAX;
            float nv = sl[0]; int nj = 0;
#pragma unroll
            for (int j = 1; j < 16; j++)
                if (sl[j] > nv) { nv = sl[j]; nj = j; }
            cv = nv; ci = nj * 256 + tid;
        }
    }
    __syncthreads();

    // scatter A: 1/16 at each selected index
    if (tid < KSEL)
        A[topk_sh[tid]] = 1.0f / (float)KSEL;

    // M = mean of 16 selected rows; thread owns dims tid, tid+256, tid+512
    {
        float a0 = 0.f, a1 = 0.f, a2 = 0.f;
#pragma unroll
        for (int k = 0; k < KSEL; k++) {
            const float* row = H + ((size_t)b * NN + topk_sh[k]) * DD;
            a0 += row[tid];
            a1 += row[tid + 256];
            a2 += row[tid + 512];
        }
        M[tid]       = a0 * (1.0f / (float)KSEL);
        M[tid + 256] = a1 * (1.0f / (float)KSEL);
        M[tid + 512] = a2 * (1.0f / (float)KSEL);
    }
    __syncthreads();

    // logits = M @ W_cls + b_cls (deterministic: warp shuffle tree + serial 8)
    float part[CC];
#pragma unroll
    for (int c = 0; c < CC; c++) part[c] = 0.0f;
    for (int d = tid; d < DD; d += 256) {
        float m = M[d];
#pragma unroll
        for (int c = 0; c < CC; c++)
            part[c] += m * W_cls[d * CC + c];
    }
#pragma unroll
    for (int c = 0; c < CC; c++) {
        float v = part[c];
#pragma unroll
        for (int off = 16; off; off >>= 1)
            v += __shfl_down_sync(0xffffffffu, v, off);
        if (lane == 0) wred[warp * CC + c] = v;
    }
    __syncthreads();

    if (tid < CC) {
        float acc = b_cls[tid];
#pragma unroll
        for (int wq = 0; wq < 8; wq++)
            acc += wred[wq * CC + tid];
        out[b * CC + tid] = acc;
    }
}

extern "C" void kernel_launch(void* const* d_in, const int* in_sizes, int n_in,
                              void* d_out, int out_size)
{
    const float* H   = (const float*)d_in[0];
    const float* w   = (const float*)d_in[1];
    const float* bs  = (const float*)d_in[2];
    const float* Wc  = (const float*)d_in[3];
    const float* bc  = (const float*)d_in[4];
    float*       out = (float*)d_out;

    score_kernel<<<(BB * NN) / 8, 256>>>(H, w, bs);
    topk_kernel<<<BB, 256>>>(H, Wc, bc, out);
}